// round 1
// baseline (speedup 1.0000x reference)
#include <cuda_runtime.h>
#include <math.h>

#define HW   4096
#define NC1  32
#define NC2  64
#define NFC1 512

// ---------------- scratch (static __device__, no allocation) ----------------
__device__ float  d_M1[NC1 * HW];                 // |FFT2(pad(w1))|      0.5 MB
__device__ float2 d_KF2[(size_t)NC2 * NC1 * HW];  // FFT2(pad(w2))        67 MB
__device__ float  d_A2[NC2 * HW];                 // layer-2 magnitude     1 MB
__device__ float  d_G[(size_t)NFC1 * HW];         // collapsed fc1         8 MB
__device__ float  d_H[10 * HW];                   // collapsed fc2@G     160 KB

// ---------------- K1: M1[i,hw] = |sum_{a,b<5} w1[i,a,b] * tw[(u*a+v*b)&63]| -
__global__ void k_m1(const float* __restrict__ w1r, const float* __restrict__ w1i) {
    __shared__ float wr[25], wi[25], twr[64], twi[64];
    const int i = blockIdx.y;
    const int tx = threadIdx.x;
    if (tx < 25) { wr[tx] = w1r[i * 25 + tx]; wi[tx] = w1i[i * 25 + tx]; }
    if (tx < 64) {
        float s, c;
        sincosf(-6.283185307179586f * (float)tx / 64.0f, &s, &c);
        twr[tx] = c; twi[tx] = s;
    }
    __syncthreads();
    const int hw = blockIdx.x * 256 + tx;
    const int u = hw >> 6, v = hw & 63;
    float re = 0.f, im = 0.f;
#pragma unroll
    for (int a = 0; a < 5; a++)
#pragma unroll
        for (int b = 0; b < 5; b++) {
            const int idx = (u * a + v * b) & 63;
            const float tr = twr[idx], ti = twi[idx];
            const float r = wr[a * 5 + b], q = wi[a * 5 + b];
            re += r * tr - q * ti;
            im += r * ti + q * tr;
        }
    d_M1[i * HW + hw] = sqrtf(re * re + im * im);
}

// ---------------- K2a: KF2[o,i,:,:] via separable 5-point DFT ---------------
__global__ void k_kf2(const float* __restrict__ w2r, const float* __restrict__ w2i) {
    __shared__ float wr[25], wi[25], twr[64], twi[64], Tr[5 * 64], Ti[5 * 64];
    const int oi = blockIdx.x;  // 0..2047  (= o*32 + i, matches w2 (64,32,5,5) layout)
    const int tx = threadIdx.x;
    if (tx < 25) { wr[tx] = w2r[oi * 25 + tx]; wi[tx] = w2i[oi * 25 + tx]; }
    if (tx < 64) {
        float s, c;
        sincosf(-6.283185307179586f * (float)tx / 64.0f, &s, &c);
        twr[tx] = c; twi[tx] = s;
    }
    __syncthreads();
    // stage 1: T[a,v] = sum_b W[a,b] * tw[(v*b)&63]
    for (int idx = tx; idx < 320; idx += 256) {
        const int a = idx >> 6, v = idx & 63;
        float re = 0.f, im = 0.f;
#pragma unroll
        for (int b = 0; b < 5; b++) {
            const int k = (v * b) & 63;
            const float tr = twr[k], ti = twi[k];
            const float r = wr[a * 5 + b], q = wi[a * 5 + b];
            re += r * tr - q * ti;
            im += r * ti + q * tr;
        }
        Tr[idx] = re; Ti[idx] = im;
    }
    __syncthreads();
    // stage 2: KF2[u,v] = sum_a tw[(u*a)&63] * T[a,v]
    const size_t base = (size_t)oi * HW;
#pragma unroll
    for (int t = 0; t < 16; t++) {
        const int hw = (t << 8) + tx;
        const int u = hw >> 6, v = hw & 63;
        float re = 0.f, im = 0.f;
#pragma unroll
        for (int a = 0; a < 5; a++) {
            const int k = (u * a) & 63;
            const float tr = twr[k], ti = twi[k];
            const float xr = Tr[a * 64 + v], xi = Ti[a * 64 + v];
            re += tr * xr - ti * xi;
            im += tr * xi + ti * xr;
        }
        d_KF2[base + hw] = make_float2(re, im);
    }
}

// ---------------- K2b: A2[o,hw] = |sum_i M1[i,hw] * KF2[o,i,hw]| -------------
__global__ void k_a2() {
    const int o = blockIdx.y;
    const int hw = blockIdx.x * 256 + threadIdx.x;
    float re = 0.f, im = 0.f;
    const size_t base = (size_t)o * NC1 * HW + hw;
#pragma unroll 8
    for (int i = 0; i < NC1; i++) {
        const float m = d_M1[i * HW + hw];
        const float2 k = d_KF2[base + (size_t)i * HW];
        re += m * k.x;
        im += m * k.y;
    }
    d_A2[o * HW + hw] = sqrtf(re * re + im * im);
}

// ---------------- zero H (atomics target, re-zeroed every launch) -----------
__global__ void k_zero_h() {
    const int i = blockIdx.x * 1024 + threadIdx.x;
    if (i < 10 * HW) d_H[i] = 0.f;
}

// ---------------- K3 (the big one): G[f,hw] = sum_o A2[o,hw]*fc1[f,o,hw] ----
// Streams 537 MB of fc1_w. A2 tile cached in smem (32 KB, static). 8 f-chains
// per thread for MLP. block=128 threads covering 512 hw (float4 each).
__global__ void __launch_bounds__(128) k_g(const float* __restrict__ fc1w) {
    __shared__ float4 a2s[16 * 128];  // 16 o-rows x 512 hw = 32 KB
    const int t = threadIdx.x;
    const int tile = blockIdx.x;      // 8 tiles of 512 hw
    const int f0 = blockIdx.y * 8;    // 64 f-chunks of 8
    const float4* __restrict__ a2g = (const float4*)d_A2;
    const float4* __restrict__ w = (const float4*)fc1w;

    float4 acc[8];
#pragma unroll
    for (int f = 0; f < 8; f++) acc[f] = make_float4(0.f, 0.f, 0.f, 0.f);

    for (int oc = 0; oc < 4; oc++) {
        __syncthreads();
        for (int idx = t; idx < 16 * 128; idx += 128) {
            const int o = idx >> 7, j = idx & 127;
            a2s[idx] = a2g[(oc * 16 + o) * 1024 + tile * 128 + j];
        }
        __syncthreads();
#pragma unroll
        for (int o = 0; o < 16; o++) {
            const float4 av = a2s[o * 128 + t];
            const size_t wb = (size_t)(oc * 16 + o) * 1024 + (size_t)tile * 128 + t;
#pragma unroll
            for (int f = 0; f < 8; f++) {
                const float4 wv = __ldcs(&w[(size_t)(f0 + f) * 65536 + wb]);
                acc[f].x += av.x * wv.x;
                acc[f].y += av.y * wv.y;
                acc[f].z += av.z * wv.z;
                acc[f].w += av.w * wv.w;
            }
        }
    }
    float4* __restrict__ g = (float4*)d_G;
#pragma unroll
    for (int f = 0; f < 8; f++)
        g[(size_t)(f0 + f) * 1024 + tile * 128 + t] = acc[f];
}

// ---------------- K4: H[c,hw] += sum_f fc2[c,f]*G[f,hw] (f split by 4) ------
__global__ void k_h(const float* __restrict__ fc2w) {
    __shared__ float fs[128 * 10];
    const int tx = threadIdx.x;
    const int hw = blockIdx.x * 256 + tx;
    const int f0 = blockIdx.y * 128;
    for (int idx = tx; idx < 1280; idx += 256) {
        const int fl = idx / 10, c = idx - fl * 10;
        fs[idx] = fc2w[c * NFC1 + f0 + fl];
    }
    __syncthreads();
    float acc[10];
#pragma unroll
    for (int c = 0; c < 10; c++) acc[c] = 0.f;
    for (int fl = 0; fl < 128; fl++) {
        const float gv = d_G[(size_t)(f0 + fl) * HW + hw];
#pragma unroll
        for (int c = 0; c < 10; c++) acc[c] += fs[fl * 10 + c] * gv;
    }
#pragma unroll
    for (int c = 0; c < 10; c++) atomicAdd(&d_H[c * HW + hw], acc[c]);
}

// ---------------- K5: out[b,c] = sum_hw |x[b,hw]|*H[c,hw] + const[c] --------
__global__ void k_out(const float* __restrict__ x,
                      const float* __restrict__ fc2w,
                      const float* __restrict__ fc1b,
                      const float* __restrict__ fc2b,
                      float* __restrict__ out) {
    const int b = blockIdx.x;
    const int tx = threadIdx.x;  // 256
    float acc[10];
#pragma unroll
    for (int c = 0; c < 10; c++) acc[c] = 0.f;
    for (int hw = tx; hw < HW; hw += 256) {
        const float a = fabsf(x[b * HW + hw]);
#pragma unroll
        for (int c = 0; c < 10; c++) acc[c] += a * d_H[c * HW + hw];
    }
    __shared__ float red[10][256];
#pragma unroll
    for (int c = 0; c < 10; c++) red[c][tx] = acc[c];
    __syncthreads();
    for (int s = 128; s > 0; s >>= 1) {
        if (tx < s) {
#pragma unroll
            for (int c = 0; c < 10; c++) red[c][tx] += red[c][tx + s];
        }
        __syncthreads();
    }
    if (tx < 10) {
        float bc = fc2b[tx];
        for (int f = 0; f < NFC1; f++) bc += fc2w[tx * NFC1 + f] * fc1b[f];
        out[b * 10 + tx] = red[tx][0] + bc;
    }
}

// ---------------- launch -----------------------------------------------------
extern "C" void kernel_launch(void* const* d_in, const int* in_sizes, int n_in,
                              void* d_out, int out_size) {
    const float* x    = (const float*)d_in[0];
    const float* w1r  = (const float*)d_in[1];
    const float* w1i  = (const float*)d_in[2];
    const float* w2r  = (const float*)d_in[3];
    const float* w2i  = (const float*)d_in[4];
    const float* fc1w = (const float*)d_in[5];
    const float* fc1b = (const float*)d_in[6];
    const float* fc2w = (const float*)d_in[7];
    const float* fc2b = (const float*)d_in[8];
    float* out = (float*)d_out;

    k_m1<<<dim3(16, 32), 256>>>(w1r, w1i);
    k_kf2<<<2048, 256>>>(w2r, w2i);
    k_a2<<<dim3(16, 64), 256>>>();
    k_zero_h<<<40, 1024>>>();
    k_g<<<dim3(8, 64), 128>>>(fc1w);
    k_h<<<dim3(16, 4), 256>>>(fc2w);
    k_out<<<32, 256>>>(x, fc2w, fc1b, fc2b, out);
}

// round 2
// speedup vs baseline: 1.0268x; 1.0268x over previous
#include <cuda_runtime.h>
#include <math.h>

#define HW   4096
#define NC1  32
#define NC2  64
#define NFC1 512

// ---------------- scratch (static __device__, no allocation) ----------------
__device__ float  d_M1[NC1 * HW];                      // |FFT2(pad(w1))|   0.5 MB
__device__ float2 d_T[(size_t)NC2 * NC1 * 5 * 64];     // row-DFT of w2     5.2 MB
__device__ float  d_A2[NC2 * HW];                      // layer-2 magnitude   1 MB
__device__ float  d_H[10 * HW];                        // fc2-collapsed     160 KB

// ---------------- K1: M1[i,hw] = |sum_{a,b<5} w1[i,a,b] * tw[(u*a+v*b)&63]| -
__global__ void k_m1(const float* __restrict__ w1r, const float* __restrict__ w1i) {
    __shared__ float wr[25], wi[25], twr[64], twi[64];
    const int i = blockIdx.y;
    const int tx = threadIdx.x;
    if (tx < 25) { wr[tx] = w1r[i * 25 + tx]; wi[tx] = w1i[i * 25 + tx]; }
    if (tx < 64) {
        float s, c;
        sincosf(-6.283185307179586f * (float)tx / 64.0f, &s, &c);
        twr[tx] = c; twi[tx] = s;
    }
    __syncthreads();
    const int hw = blockIdx.x * 256 + tx;
    const int u = hw >> 6, v = hw & 63;
    float re = 0.f, im = 0.f;
#pragma unroll
    for (int a = 0; a < 5; a++)
#pragma unroll
        for (int b = 0; b < 5; b++) {
            const int idx = (u * a + v * b) & 63;
            const float tr = twr[idx], ti = twi[idx];
            const float r = wr[a * 5 + b], q = wi[a * 5 + b];
            re += r * tr - q * ti;
            im += r * ti + q * tr;
        }
    d_M1[i * HW + hw] = sqrtf(re * re + im * im);
}

// ---------------- K2: T[oi,a,v] = sum_b w2c[oi,a,b] * tw[(v*b)&63] ----------
__global__ void k_T(const float* __restrict__ w2r, const float* __restrict__ w2i) {
    __shared__ float twr[64], twi[64];
    const int tx = threadIdx.x;
    if (tx < 64) {
        float s, c;
        sincosf(-6.283185307179586f * (float)tx / 64.0f, &s, &c);
        twr[tx] = c; twi[tx] = s;
    }
    __syncthreads();
    const int gi = blockIdx.x * 256 + tx;       // 0 .. 655359
    const int v = gi & 63;
    const int rest = gi >> 6;                   // oi*5 + a
    const int a = rest % 5;
    const int oi = rest / 5;
    float re = 0.f, im = 0.f;
#pragma unroll
    for (int b = 0; b < 5; b++) {
        const int k = (v * b) & 63;
        const float r = w2r[oi * 25 + a * 5 + b];
        const float q = w2i[oi * 25 + a * 5 + b];
        re += r * twr[k] - q * twi[k];
        im += r * twi[k] + q * twr[k];
    }
    d_T[gi] = make_float2(re, im);
}

// ---------------- K3: A2[o,hw] = |sum_i M1[i,hw] * sum_a tw(ua)*T[o,i,a,v]| -
// Fuses the u-direction DFT with the input-channel accumulation; never
// materializes the 67 MB KF2 tensor.
__global__ void __launch_bounds__(256) k_a2f() {
    __shared__ float Tr[8 * 320], Tim[8 * 320];   // 8 i x 5 a x 64 v
    __shared__ float M1s[8 * 256];
    __shared__ float twr[64], twi[64];
    const int tx = threadIdx.x;
    const int o = blockIdx.y;
    const int tile = blockIdx.x;                  // 16 tiles of 256 hw
    const int hw = tile * 256 + tx;
    const int u = hw >> 6, v = hw & 63;
    if (tx < 64) {
        float s, c;
        sincosf(-6.283185307179586f * (float)tx / 64.0f, &s, &c);
        twr[tx] = c; twi[tx] = s;
    }
    __syncthreads();
    float tur[5], tui[5];
#pragma unroll
    for (int a = 0; a < 5; a++) {
        const int k = (u * a) & 63;
        tur[a] = twr[k]; tui[a] = twi[k];
    }
    const float2* __restrict__ T = d_T + (size_t)o * (NC1 * 320);
    float re = 0.f, im = 0.f;
    for (int c = 0; c < 4; c++) {                 // i-chunks of 8
        __syncthreads();
        for (int idx = tx; idx < 8 * 320; idx += 256) {
            const float2 t = T[c * 8 * 320 + idx];
            Tr[idx] = t.x; Tim[idx] = t.y;
        }
        for (int idx = tx; idx < 8 * 256; idx += 256) {
            const int ii = idx >> 8, j = idx & 255;
            M1s[idx] = d_M1[(c * 8 + ii) * HW + tile * 256 + j];
        }
        __syncthreads();
#pragma unroll
        for (int ii = 0; ii < 8; ii++) {
            const float m = M1s[ii * 256 + tx];
            float kr = 0.f, ki = 0.f;
#pragma unroll
            for (int a = 0; a < 5; a++) {
                const float tr = Tr[ii * 320 + a * 64 + v];
                const float ti = Tim[ii * 320 + a * 64 + v];
                kr += tur[a] * tr - tui[a] * ti;
                ki += tur[a] * ti + tui[a] * tr;
            }
            re += m * kr;
            im += m * ki;
        }
    }
    d_A2[o * HW + hw] = sqrtf(re * re + im * im);
}

// ---------------- zero H (split in two so k_g is ncu launch index 5) --------
__global__ void k_zero_a() {
    const int i = blockIdx.x * 1024 + threadIdx.x;
    if (i < 5 * HW) d_H[i] = 0.f;
}
__global__ void k_zero_b() {
    const int i = 5 * HW + blockIdx.x * 1024 + threadIdx.x;
    if (i < 10 * HW) d_H[i] = 0.f;
}

// ---------------- K4 (dominant): stream fc1_w, fold fc2 in epilogue ---------
// H[c,hw] += sum_f fc2[c,f] * sum_o A2[o,hw] * fc1[f,o,hw]
__global__ void __launch_bounds__(128) k_g(const float* __restrict__ fc1w,
                                           const float* __restrict__ fc2w) {
    __shared__ float4 a2s[16 * 128];              // 16 o-rows x 512 hw = 32 KB
    __shared__ float fc2s[10][8];
    const int t = threadIdx.x;
    const int tile = blockIdx.x;                  // 8 tiles of 512 hw
    const int f0 = blockIdx.y * 8;                // 64 f-chunks of 8
    if (t < 80) {
        const int c = t >> 3, f = t & 7;
        fc2s[c][f] = fc2w[c * NFC1 + f0 + f];
    }
    const float4* __restrict__ a2g = (const float4*)d_A2;
    const float4* __restrict__ w = (const float4*)fc1w;

    float4 acc[8];
#pragma unroll
    for (int f = 0; f < 8; f++) acc[f] = make_float4(0.f, 0.f, 0.f, 0.f);

    for (int oc = 0; oc < 4; oc++) {
        __syncthreads();
        for (int idx = t; idx < 16 * 128; idx += 128) {
            const int o = idx >> 7, j = idx & 127;
            a2s[idx] = a2g[(oc * 16 + o) * 1024 + tile * 128 + j];
        }
        __syncthreads();
#pragma unroll
        for (int o = 0; o < 16; o++) {
            const float4 av = a2s[o * 128 + t];
            const size_t wb = (size_t)(oc * 16 + o) * 1024 + (size_t)tile * 128 + t;
#pragma unroll
            for (int f = 0; f < 8; f++) {
                const float4 wv = __ldcs(&w[(size_t)(f0 + f) * 65536 + wb]);
                acc[f].x += av.x * wv.x;
                acc[f].y += av.y * wv.y;
                acc[f].z += av.z * wv.z;
                acc[f].w += av.w * wv.w;
            }
        }
    }
    // epilogue: contract the 8 f's against fc2 and accumulate into H
    const int hwb = (tile * 128 + t) * 4;
#pragma unroll
    for (int c = 0; c < 10; c++) {
        float hx = 0.f, hy = 0.f, hz = 0.f, hww = 0.f;
#pragma unroll
        for (int f = 0; f < 8; f++) {
            const float s = fc2s[c][f];
            hx += s * acc[f].x;
            hy += s * acc[f].y;
            hz += s * acc[f].z;
            hww += s * acc[f].w;
        }
        float* Hp = &d_H[c * HW + hwb];
        atomicAdd(Hp + 0, hx);
        atomicAdd(Hp + 1, hy);
        atomicAdd(Hp + 2, hz);
        atomicAdd(Hp + 3, hww);
    }
}

// ---------------- K5: out[b,c] = sum_hw |x[b,hw]|*H[c,hw] + const[c] --------
__global__ void k_out(const float* __restrict__ x,
                      const float* __restrict__ fc2w,
                      const float* __restrict__ fc1b,
                      const float* __restrict__ fc2b,
                      float* __restrict__ out) {
    const int b = blockIdx.x;
    const int tx = threadIdx.x;  // 256
    float acc[10];
#pragma unroll
    for (int c = 0; c < 10; c++) acc[c] = 0.f;
    for (int hw = tx; hw < HW; hw += 256) {
        const float a = fabsf(x[b * HW + hw]);
#pragma unroll
        for (int c = 0; c < 10; c++) acc[c] += a * d_H[c * HW + hw];
    }
    __shared__ float red[10][256];
#pragma unroll
    for (int c = 0; c < 10; c++) red[c][tx] = acc[c];
    __syncthreads();
    for (int s = 128; s > 0; s >>= 1) {
        if (tx < s) {
#pragma unroll
            for (int c = 0; c < 10; c++) red[c][tx] += red[c][tx + s];
        }
        __syncthreads();
    }
    if (tx < 10) {
        float bc = fc2b[tx];
        for (int f = 0; f < NFC1; f++) bc += fc2w[tx * NFC1 + f] * fc1b[f];
        out[b * 10 + tx] = red[tx][0] + bc;
    }
}

// ---------------- launch -----------------------------------------------------
extern "C" void kernel_launch(void* const* d_in, const int* in_sizes, int n_in,
                              void* d_out, int out_size) {
    const float* x    = (const float*)d_in[0];
    const float* w1r  = (const float*)d_in[1];
    const float* w1i  = (const float*)d_in[2];
    const float* w2r  = (const float*)d_in[3];
    const float* w2i  = (const float*)d_in[4];
    const float* fc1w = (const float*)d_in[5];
    const float* fc1b = (const float*)d_in[6];
    const float* fc2w = (const float*)d_in[7];
    const float* fc2b = (const float*)d_in[8];
    float* out = (float*)d_out;

    k_m1 <<<dim3(16, 32), 256>>>(w1r, w1i);   // launch 0
    k_T  <<<2560, 256>>>(w2r, w2i);           // launch 1
    k_a2f<<<dim3(16, 64), 256>>>();           // launch 2
    k_zero_a<<<20, 1024>>>();                 // launch 3
    k_zero_b<<<20, 1024>>>();                 // launch 4
    k_g  <<<dim3(8, 64), 128>>>(fc1w, fc2w);  // launch 5 (ncu -s 5 target)
    k_out<<<32, 256>>>(x, fc2w, fc1b, fc2b, out);
}

// round 3
// speedup vs baseline: 1.0553x; 1.0277x over previous
#include <cuda_runtime.h>
#include <math.h>

#define HW   4096
#define NC1  32
#define NC2  64
#define NFC1 512

// ---------------- scratch (static __device__, no allocation) ----------------
__device__ float  d_M1[NC1 * HW];                      // |FFT2(pad(w1))|   0.5 MB
__device__ float2 d_T[(size_t)NC2 * NC1 * 5 * 64];     // row-DFT of w2     5.2 MB
__device__ float  d_A2[NC2 * HW];                      // layer-2 magnitude   1 MB
__device__ float  d_H[10 * HW];                        // fc2-collapsed     160 KB
__device__ float  d_biasv[10];                         // fc2b + fc2w@fc1b

// ---------------- L0 prep: M1 DFT + T row-DFT + zero H, block-dispatched ----
// blocks [0,512): M1      blocks [512,3072): T      blocks [3072,3082): zero H
__global__ void __launch_bounds__(256) k_prep(const float* __restrict__ w1r,
                                              const float* __restrict__ w1i,
                                              const float* __restrict__ w2r,
                                              const float* __restrict__ w2i) {
    __shared__ float twr[64], twi[64], wr[25], wi[25];
    const int bx = blockIdx.x;
    const int tx = threadIdx.x;
    if (tx < 64) {
        float s, c;
        sincosf(-6.283185307179586f * (float)tx / 64.0f, &s, &c);
        twr[tx] = c; twi[tx] = s;
    }
    if (bx < 512) {
        // ---- M1[i,hw] = |sum_{a,b} w1[i,a,b] tw(ua+vb)| ----
        const int i = bx >> 4, tile = bx & 15;
        if (tx < 25) { wr[tx] = w1r[i * 25 + tx]; wi[tx] = w1i[i * 25 + tx]; }
        __syncthreads();
        const int hw = tile * 256 + tx;
        const int u = hw >> 6, v = hw & 63;
        float re = 0.f, im = 0.f;
#pragma unroll
        for (int a = 0; a < 5; a++)
#pragma unroll
            for (int b = 0; b < 5; b++) {
                const int idx = (u * a + v * b) & 63;
                const float tr = twr[idx], ti = twi[idx];
                const float r = wr[a * 5 + b], q = wi[a * 5 + b];
                re += r * tr - q * ti;
                im += r * ti + q * tr;
            }
        d_M1[i * HW + hw] = sqrtf(re * re + im * im);
    } else if (bx < 3072) {
        // ---- T[oi,a,v] = sum_b w2c[oi,a,b] tw(vb) ----
        __syncthreads();
        const int gi = (bx - 512) * 256 + tx;   // 0 .. 655359
        const int v = gi & 63;
        const int rest = gi >> 6;               // oi*5 + a
        const int a = rest % 5;
        const int oi = rest / 5;
        float re = 0.f, im = 0.f;
#pragma unroll
        for (int b = 0; b < 5; b++) {
            const int k = (v * b) & 63;
            const float r = w2r[oi * 25 + a * 5 + b];
            const float q = w2i[oi * 25 + a * 5 + b];
            re += r * twr[k] - q * twi[k];
            im += r * twi[k] + q * twr[k];
        }
        d_T[gi] = make_float2(re, im);
    } else {
        // ---- zero H (40960 floats over 10 blocks) ----
        const int base = (bx - 3072) * 4096;
#pragma unroll
        for (int k = 0; k < 16; k++) d_H[base + k * 256 + tx] = 0.f;
    }
}

// ---------------- L1: A2[o,hw] = |sum_i M1[i,hw] * sum_a tw(ua)*T[o,i,a,v]| -
__global__ void __launch_bounds__(256) k_a2f() {
    __shared__ float Tr[8 * 320], Tim[8 * 320];   // 8 i x 5 a x 64 v
    __shared__ float M1s[8 * 256];
    __shared__ float twr[64], twi[64];
    const int tx = threadIdx.x;
    const int o = blockIdx.y;
    const int tile = blockIdx.x;                  // 16 tiles of 256 hw
    const int hw = tile * 256 + tx;
    const int u = hw >> 6, v = hw & 63;
    if (tx < 64) {
        float s, c;
        sincosf(-6.283185307179586f * (float)tx / 64.0f, &s, &c);
        twr[tx] = c; twi[tx] = s;
    }
    __syncthreads();
    float tur[5], tui[5];
#pragma unroll
    for (int a = 0; a < 5; a++) {
        const int k = (u * a) & 63;
        tur[a] = twr[k]; tui[a] = twi[k];
    }
    const float2* __restrict__ T = d_T + (size_t)o * (NC1 * 320);
    float re = 0.f, im = 0.f;
    for (int c = 0; c < 4; c++) {                 // i-chunks of 8
        __syncthreads();
        for (int idx = tx; idx < 8 * 320; idx += 256) {
            const float2 t = T[c * 8 * 320 + idx];
            Tr[idx] = t.x; Tim[idx] = t.y;
        }
        for (int idx = tx; idx < 8 * 256; idx += 256) {
            const int ii = idx >> 8, j = idx & 255;
            M1s[idx] = d_M1[(c * 8 + ii) * HW + tile * 256 + j];
        }
        __syncthreads();
#pragma unroll
        for (int ii = 0; ii < 8; ii++) {
            const float m = M1s[ii * 256 + tx];
            float kr = 0.f, ki = 0.f;
#pragma unroll
            for (int a = 0; a < 5; a++) {
                const float tr = Tr[ii * 320 + a * 64 + v];
                const float ti = Tim[ii * 320 + a * 64 + v];
                kr += tur[a] * tr - tui[a] * ti;
                ki += tur[a] * ti + tui[a] * tr;
            }
            re += m * kr;
            im += m * ki;
        }
    }
    d_A2[o * HW + hw] = sqrtf(re * re + im * im);
}

// ---------------- L2: bias constant (also the ncu index spacer) -------------
__global__ void k_bias(const float* __restrict__ fc2w,
                       const float* __restrict__ fc1b,
                       const float* __restrict__ fc2b) {
    const int c = threadIdx.x;
    if (c < 10) {
        float bc = fc2b[c];
        for (int f = 0; f < NFC1; f++) bc += fc2w[c * NFC1 + f] * fc1b[f];
        d_biasv[c] = bc;
    }
}

// ---------------- L3 (dominant, ncu target): stream fc1_w -------------------
// H[c,hw] += sum_f fc2[c,f] * sum_o A2[o,hw] * fc1[f,o,hw]
__global__ void __launch_bounds__(128) k_g(const float* __restrict__ fc1w,
                                           const float* __restrict__ fc2w) {
    __shared__ float4 a2s[16 * 128];              // 16 o-rows x 512 hw = 32 KB
    __shared__ float fc2s[10][8];
    const int t = threadIdx.x;
    const int tile = blockIdx.x;                  // 8 tiles of 512 hw
    const int f0 = blockIdx.y * 8;                // 64 f-chunks of 8
    if (t < 80) {
        const int c = t >> 3, f = t & 7;
        fc2s[c][f] = fc2w[c * NFC1 + f0 + f];
    }
    const float4* __restrict__ a2g = (const float4*)d_A2;
    const float4* __restrict__ w = (const float4*)fc1w;

    float4 acc[8];
#pragma unroll
    for (int f = 0; f < 8; f++) acc[f] = make_float4(0.f, 0.f, 0.f, 0.f);

    for (int oc = 0; oc < 4; oc++) {
        __syncthreads();
        for (int idx = t; idx < 16 * 128; idx += 128) {
            const int o = idx >> 7, j = idx & 127;
            a2s[idx] = a2g[(oc * 16 + o) * 1024 + tile * 128 + j];
        }
        __syncthreads();
#pragma unroll
        for (int o = 0; o < 16; o++) {
            const float4 av = a2s[o * 128 + t];
            const size_t wb = (size_t)(oc * 16 + o) * 1024 + (size_t)tile * 128 + t;
#pragma unroll
            for (int f = 0; f < 8; f++) {
                const float4 wv = __ldcs(&w[(size_t)(f0 + f) * 65536 + wb]);
                acc[f].x += av.x * wv.x;
                acc[f].y += av.y * wv.y;
                acc[f].z += av.z * wv.z;
                acc[f].w += av.w * wv.w;
            }
        }
    }
    const int hwb = (tile * 128 + t) * 4;
#pragma unroll
    for (int c = 0; c < 10; c++) {
        float hx = 0.f, hy = 0.f, hz = 0.f, hww = 0.f;
#pragma unroll
        for (int f = 0; f < 8; f++) {
            const float s = fc2s[c][f];
            hx += s * acc[f].x;
            hy += s * acc[f].y;
            hz += s * acc[f].z;
            hww += s * acc[f].w;
        }
        float* Hp = &d_H[c * HW + hwb];
        atomicAdd(Hp + 0, hx);
        atomicAdd(Hp + 1, hy);
        atomicAdd(Hp + 2, hz);
        atomicAdd(Hp + 3, hww);
    }
}

// ---------------- L4: out[b,c] = sum_hw |x[b,hw]|*H[c,hw] + biasv[c] --------
__global__ void k_out(const float* __restrict__ x, float* __restrict__ out) {
    const int b = blockIdx.x;
    const int tx = threadIdx.x;  // 256
    float acc[10];
#pragma unroll
    for (int c = 0; c < 10; c++) acc[c] = 0.f;
    for (int hw = tx; hw < HW; hw += 256) {
        const float a = fabsf(x[b * HW + hw]);
#pragma unroll
        for (int c = 0; c < 10; c++) acc[c] += a * d_H[c * HW + hw];
    }
    __shared__ float red[10][256];
#pragma unroll
    for (int c = 0; c < 10; c++) red[c][tx] = acc[c];
    __syncthreads();
    for (int s = 128; s > 0; s >>= 1) {
        if (tx < s) {
#pragma unroll
            for (int c = 0; c < 10; c++) red[c][tx] += red[c][tx + s];
        }
        __syncthreads();
    }
    if (tx < 10) out[b * 10 + tx] = red[tx][0] + d_biasv[tx];
}

// ---------------- launch -----------------------------------------------------
extern "C" void kernel_launch(void* const* d_in, const int* in_sizes, int n_in,
                              void* d_out, int out_size) {
    const float* x    = (const float*)d_in[0];
    const float* w1r  = (const float*)d_in[1];
    const float* w1i  = (const float*)d_in[2];
    const float* w2r  = (const float*)d_in[3];
    const float* w2i  = (const float*)d_in[4];
    const float* fc1w = (const float*)d_in[5];
    const float* fc1b = (const float*)d_in[6];
    const float* fc2w = (const float*)d_in[7];
    const float* fc2b = (const float*)d_in[8];
    float* out = (float*)d_out;

    k_prep<<<3082, 256>>>(w1r, w1i, w2r, w2i);      // launch 0
    k_a2f <<<dim3(16, 64), 256>>>();                // launch 1
    k_bias<<<1, 32>>>(fc2w, fc1b, fc2b);            // launch 2
    k_g   <<<dim3(8, 64), 128>>>(fc1w, fc2w);       // launch 3  <- ncu target
    k_out <<<32, 256>>>(x, out);                    // launch 4
}

// round 4
// speedup vs baseline: 1.0996x; 1.0420x over previous
#include <cuda_runtime.h>
#include <math.h>

#define HW   4096
#define NC1  32
#define NC2  64
#define NFC1 512

// ---------------- scratch (static __device__, no allocation) ----------------
__device__ float  d_M1[NC1 * HW];                      // |FFT2(pad(w1))|   0.5 MB
__device__ float2 d_T[(size_t)NC2 * NC1 * 5 * 64];     // row-DFT of w2     5.2 MB
__device__ float  d_A2[NC2 * HW];                      // layer-2 magnitude   1 MB
__device__ float  d_H[10 * HW];                        // fc2-collapsed     160 KB
__device__ float  d_biasv[10];                         // fc2b + fc2w@fc1b

// ---------------- L0 prep: M1 DFT + T row-DFT + zero H, block-dispatched ----
__global__ void __launch_bounds__(256) k_prep(const float* __restrict__ w1r,
                                              const float* __restrict__ w1i,
                                              const float* __restrict__ w2r,
                                              const float* __restrict__ w2i) {
    __shared__ float twr[64], twi[64], wr[25], wi[25];
    const int bx = blockIdx.x;
    const int tx = threadIdx.x;
    if (tx < 64) {
        float s, c;
        sincosf(-6.283185307179586f * (float)tx / 64.0f, &s, &c);
        twr[tx] = c; twi[tx] = s;
    }
    if (bx < 512) {
        const int i = bx >> 4, tile = bx & 15;
        if (tx < 25) { wr[tx] = w1r[i * 25 + tx]; wi[tx] = w1i[i * 25 + tx]; }
        __syncthreads();
        const int hw = tile * 256 + tx;
        const int u = hw >> 6, v = hw & 63;
        float re = 0.f, im = 0.f;
#pragma unroll
        for (int a = 0; a < 5; a++)
#pragma unroll
            for (int b = 0; b < 5; b++) {
                const int idx = (u * a + v * b) & 63;
                const float tr = twr[idx], ti = twi[idx];
                const float r = wr[a * 5 + b], q = wi[a * 5 + b];
                re += r * tr - q * ti;
                im += r * ti + q * tr;
            }
        d_M1[i * HW + hw] = sqrtf(re * re + im * im);
    } else if (bx < 3072) {
        __syncthreads();
        const int gi = (bx - 512) * 256 + tx;
        const int v = gi & 63;
        const int rest = gi >> 6;
        const int a = rest % 5;
        const int oi = rest / 5;
        float re = 0.f, im = 0.f;
#pragma unroll
        for (int b = 0; b < 5; b++) {
            const int k = (v * b) & 63;
            const float r = w2r[oi * 25 + a * 5 + b];
            const float q = w2i[oi * 25 + a * 5 + b];
            re += r * twr[k] - q * twi[k];
            im += r * twi[k] + q * twr[k];
        }
        d_T[gi] = make_float2(re, im);
    } else {
        const int base = (bx - 3072) * 4096;
#pragma unroll
        for (int k = 0; k < 16; k++) d_H[base + k * 256 + tx] = 0.f;
    }
}

// ---------------- L1: A2[o,hw] = |sum_i M1[i,hw] * sum_a tw(ua)*T[o,i,a,v]| -
// T staged in smem as interleaved float2 (one LDS.64 per (i,a) term).
__global__ void __launch_bounds__(256) k_a2f() {
    __shared__ float2 Ts[8 * 320];                // 8 i x 5 a x 64 v, 12.8 KB
    __shared__ float M1s[8 * 256];
    __shared__ float twr[64], twi[64];
    const int tx = threadIdx.x;
    const int o = blockIdx.y;
    const int tile = blockIdx.x;                  // 16 tiles of 256 hw
    const int hw = tile * 256 + tx;
    const int u = hw >> 6, v = hw & 63;
    if (tx < 64) {
        float s, c;
        sincosf(-6.283185307179586f * (float)tx / 64.0f, &s, &c);
        twr[tx] = c; twi[tx] = s;
    }
    __syncthreads();
    float tur[5], tui[5];
#pragma unroll
    for (int a = 0; a < 5; a++) {
        const int k = (u * a) & 63;
        tur[a] = twr[k]; tui[a] = twi[k];
    }
    const float2* __restrict__ T = d_T + (size_t)o * (NC1 * 320);
    float re = 0.f, im = 0.f;
    for (int c = 0; c < 4; c++) {                 // i-chunks of 8
        __syncthreads();
        for (int idx = tx; idx < 8 * 320; idx += 256)
            Ts[idx] = T[c * 8 * 320 + idx];
        for (int idx = tx; idx < 8 * 256; idx += 256) {
            const int ii = idx >> 8, j = idx & 255;
            M1s[idx] = d_M1[(c * 8 + ii) * HW + tile * 256 + j];
        }
        __syncthreads();
#pragma unroll
        for (int ii = 0; ii < 8; ii++) {
            const float m = M1s[ii * 256 + tx];
            float kr = 0.f, ki = 0.f;
#pragma unroll
            for (int a = 0; a < 5; a++) {
                const float2 tt = Ts[ii * 320 + a * 64 + v];
                kr += tur[a] * tt.x - tui[a] * tt.y;
                ki += tur[a] * tt.y + tui[a] * tt.x;
            }
            re += m * kr;
            im += m * ki;
        }
    }
    d_A2[o * HW + hw] = sqrtf(re * re + im * im);
}

// ---------------- L2: bias constant (ncu index spacer) ----------------------
__global__ void k_bias(const float* __restrict__ fc2w,
                       const float* __restrict__ fc1b,
                       const float* __restrict__ fc2b) {
    const int c = threadIdx.x;
    if (c < 10) {
        float bc = fc2b[c];
        for (int f = 0; f < NFC1; f++) bc += fc2w[c * NFC1 + f] * fc1b[f];
        d_biasv[c] = bc;
    }
}

// ---------------- L3 (dominant): stream fc1_w, single-wave occupancy --------
// grid (8 tiles, 128 f-chunks of 4) = 1024 blocks, 16 KB smem, <=64 regs.
__global__ void __launch_bounds__(128, 8) k_g(const float* __restrict__ fc1w,
                                              const float* __restrict__ fc2w) {
    __shared__ float4 a2s[8 * 128];               // 8 o-rows x 512 hw = 16 KB
    __shared__ float fc2s[10][4];
    const int t = threadIdx.x;
    const int tile = blockIdx.x;                  // 8 tiles of 512 hw
    const int f0 = blockIdx.y * 4;                // 128 f-chunks of 4
    if (t < 40) {
        const int c = t >> 2, f = t & 3;
        fc2s[c][f] = fc2w[c * NFC1 + f0 + f];
    }
    const float4* __restrict__ a2g = (const float4*)d_A2;
    const float4* __restrict__ w = (const float4*)fc1w;

    float4 acc[4];
#pragma unroll
    for (int f = 0; f < 4; f++) acc[f] = make_float4(0.f, 0.f, 0.f, 0.f);

    for (int oc = 0; oc < 8; oc++) {              // 8 chunks of 8 o-rows
        __syncthreads();
        for (int idx = t; idx < 8 * 128; idx += 128) {
            const int o = idx >> 7, j = idx & 127;
            a2s[idx] = a2g[(oc * 8 + o) * 1024 + tile * 128 + j];
        }
        __syncthreads();
#pragma unroll
        for (int o = 0; o < 8; o++) {
            const float4 av = a2s[o * 128 + t];
            const size_t wb = (size_t)(oc * 8 + o) * 1024 + (size_t)tile * 128 + t;
#pragma unroll
            for (int f = 0; f < 4; f++) {
                const float4 wv = __ldcs(&w[(size_t)(f0 + f) * 65536 + wb]);
                acc[f].x += av.x * wv.x;
                acc[f].y += av.y * wv.y;
                acc[f].z += av.z * wv.z;
                acc[f].w += av.w * wv.w;
            }
        }
    }
    const int hwb = (tile * 128 + t) * 4;
#pragma unroll
    for (int c = 0; c < 10; c++) {
        float hx = 0.f, hy = 0.f, hz = 0.f, hww = 0.f;
#pragma unroll
        for (int f = 0; f < 4; f++) {
            const float s = fc2s[c][f];
            hx += s * acc[f].x;
            hy += s * acc[f].y;
            hz += s * acc[f].z;
            hww += s * acc[f].w;
        }
        float* Hp = &d_H[c * HW + hwb];
        atomicAdd(Hp + 0, hx);
        atomicAdd(Hp + 1, hy);
        atomicAdd(Hp + 2, hz);
        atomicAdd(Hp + 3, hww);
    }
}

// ---------------- L4: out[b,c] = sum_hw |x[b,hw]|*H[c,hw] + biasv[c] --------
__global__ void k_out(const float* __restrict__ x, float* __restrict__ out) {
    const int b = blockIdx.x;
    const int tx = threadIdx.x;  // 256
    float acc[10];
#pragma unroll
    for (int c = 0; c < 10; c++) acc[c] = 0.f;
    for (int hw = tx; hw < HW; hw += 256) {
        const float a = fabsf(x[b * HW + hw]);
#pragma unroll
        for (int c = 0; c < 10; c++) acc[c] += a * d_H[c * HW + hw];
    }
    __shared__ float red[10][256];
#pragma unroll
    for (int c = 0; c < 10; c++) red[c][tx] = acc[c];
    __syncthreads();
    for (int s = 128; s > 0; s >>= 1) {
        if (tx < s) {
#pragma unroll
            for (int c = 0; c < 10; c++) red[c][tx] += red[c][tx + s];
        }
        __syncthreads();
    }
    if (tx < 10) out[b * 10 + tx] = red[tx][0] + d_biasv[tx];
}

// ---------------- launch -----------------------------------------------------
extern "C" void kernel_launch(void* const* d_in, const int* in_sizes, int n_in,
                              void* d_out, int out_size) {
    const float* x    = (const float*)d_in[0];
    const float* w1r  = (const float*)d_in[1];
    const float* w1i  = (const float*)d_in[2];
    const float* w2r  = (const float*)d_in[3];
    const float* w2i  = (const float*)d_in[4];
    const float* fc1w = (const float*)d_in[5];
    const float* fc1b = (const float*)d_in[6];
    const float* fc2w = (const float*)d_in[7];
    const float* fc2b = (const float*)d_in[8];
    float* out = (float*)d_out;

    k_prep<<<3082, 256>>>(w1r, w1i, w2r, w2i);      // launch 0
    k_a2f <<<dim3(16, 64), 256>>>();                // launch 1
    k_bias<<<1, 32>>>(fc2w, fc1b, fc2b);            // launch 2
    k_g   <<<dim3(8, 128), 128>>>(fc1w, fc2w);      // launch 3  <- ncu target
    k_out <<<32, 256>>>(x, out);                    // launch 4
}